// round 3
// baseline (speedup 1.0000x reference)
#include <cuda_runtime.h>
#include <cstdint>

// Problem constants (Phi-3-small blocksparse prompt attention)
#define TOKENS   2048
#define NHEADS   32
#define NKV      8
#define HDIM     128
#define NBLK     32          // 2048 / 64
#define LOCALB   16
#define VSTRIDE  8
#define QKSCALE  0.08838834764831845f

// Shared memory strides (floats), chosen for conflict-free LDS.128 access
#define SQ  132              // Q row stride
#define SKV 132              // K/V row stride
#define SP  80               // P row stride

// Shared memory layout (float offsets)
#define OFF_Q   0
#define OFF_KV  (64 * SQ)                    // 8448
#define KVBUF   (2 * 64 * SKV)               // K tile + V tile per buffer = 16896
#define OFF_P   (OFF_KV + 2 * KVBUF)         // 42240
#define SMEM_F  (OFF_P + 64 * SP)            // 47360 floats = 189440 bytes

__device__ __forceinline__ void cpasync16(float* dst, const float* src) {
    unsigned s = (unsigned)__cvta_generic_to_shared(dst);
    asm volatile("cp.async.cg.shared.global [%0], [%1], 16;\n"
                 :: "r"(s), "l"(src) : "memory");
}
__device__ __forceinline__ void cp_commit() {
    asm volatile("cp.async.commit_group;\n" ::: "memory");
}
__device__ __forceinline__ void cp_wait1() {
    asm volatile("cp.async.wait_group 1;\n" ::: "memory");
}

// Stage one 64x128 K tile and one 64x128 V tile into smem buffer `buf`.
__device__ __forceinline__ void load_kv_tile(float* sm, int buf, int kb,
                                             const float* __restrict__ kg,
                                             const float* __restrict__ vg,
                                             int hkv, int tid) {
    float* Ks = sm + OFF_KV + buf * KVBUF;
    float* Vs = Ks + 64 * SKV;
    const float* kp = kg + (size_t)(kb * 64) * (NKV * HDIM) + hkv * HDIM;
    const float* vp = vg + (size_t)(kb * 64) * (NKV * HDIM) + hkv * HDIM;
#pragma unroll
    for (int u = 0; u < 8; ++u) {
        int t = tid + u * 256;
        int r = t >> 5;              // 64 rows, 32 chunks of 16B per row
        int c = (t & 31) << 2;       // float offset, 16B aligned
        cpasync16(Ks + r * SKV + c, kp + r * (NKV * HDIM) + c);
        cpasync16(Vs + r * SKV + c, vp + r * (NKV * HDIM) + c);
    }
}

__global__ void __launch_bounds__(256, 1)
bsattn_fp32_kernel(const float* __restrict__ q,
                   const float* __restrict__ k,
                   const float* __restrict__ v,
                   float* __restrict__ out) {
    extern __shared__ float sm[];
    const int tid = threadIdx.x;
    const int tx = tid & 15;          // 16 cols of thread grid
    const int ty = tid >> 4;          // 16 rows of thread grid
    const int bid = blockIdx.x;
    const int h  = bid & 31;
    const int qb = (NBLK - 1) - (bid >> 5);   // big q-blocks scheduled first
    const int hkv = h >> 2;                   // GQA: 4 query heads per kv head

    // ---- enumerate allowed key blocks: verticals (kb <= qb-16) then locals ----
    const int kb0 = (VSTRIDE - ((h + 1) & (VSTRIDE - 1))) & (VSTRIDE - 1);
    int nvert = 0;
    if (qb >= LOCALB && kb0 <= qb - LOCALB)
        nvert = (qb - LOCALB - kb0) / VSTRIDE + 1;
    int lstart = qb - (LOCALB - 1); if (lstart < 0) lstart = 0;
    const int nloc = qb - lstart + 1;
    const int nbt  = nvert + nloc;

    float* Qs = sm + OFF_Q;
    float* Ps = sm + OFF_P;

    // ---- prologue: prefetch first two K/V tiles (always commit 2 groups) ----
    {
        int kb_first = (0 < nvert) ? kb0 : lstart;
        load_kv_tile(sm, 0, kb_first, k, v, hkv, tid);
    }
    cp_commit();
    if (nbt > 1) {
        int kb_second = (1 < nvert) ? (kb0 + VSTRIDE) : (lstart + 1 - nvert);
        load_kv_tile(sm, 1, kb_second, k, v, hkv, tid);
    }
    cp_commit();

    // ---- load Q tile, pre-scaled by 1/sqrt(D) ----
    {
        const float* qg = q + (size_t)(qb * 64) * (NHEADS * HDIM) + h * HDIM;
#pragma unroll
        for (int u = 0; u < 8; ++u) {
            int t = tid + u * 256;
            int r = t >> 5;
            int c = (t & 31) << 2;
            float4 val = *(const float4*)(qg + r * (NHEADS * HDIM) + c);
            val.x *= QKSCALE; val.y *= QKSCALE; val.z *= QKSCALE; val.w *= QKSCALE;
            *(float4*)(Qs + r * SQ + c) = val;
        }
    }

    // ---- online-softmax state: thread owns rows {ty, ty+16, ty+32, ty+48} ----
    float m[4], l[4], o[4][8];
#pragma unroll
    for (int i = 0; i < 4; ++i) {
        m[i] = -1e30f; l[i] = 0.f;
#pragma unroll
        for (int jj = 0; jj < 8; ++jj) o[i][jj] = 0.f;
    }

    for (int it = 0; it < nbt; ++it) {
        const int kb = (it < nvert) ? (kb0 + VSTRIDE * it) : (lstart + it - nvert);
        float* Ks = sm + OFF_KV + (it & 1) * KVBUF;
        float* Vs = Ks + 64 * SKV;

        cp_wait1();            // tile `it` landed (at most the it+1 load in flight)
        __syncthreads();       // visible to all threads; prev PV done reading P

        // ---- QK: S[r][c] = Q[r]. K[c], 4x4 microtile, interleaved by 16 ----
        float s[4][4];
#pragma unroll
        for (int i = 0; i < 4; ++i)
#pragma unroll
            for (int j = 0; j < 4; ++j) s[i][j] = 0.f;

#pragma unroll 4
        for (int d4 = 0; d4 < HDIM / 4; ++d4) {
            float4 qv[4], kv4[4];
#pragma unroll
            for (int i = 0; i < 4; ++i)
                qv[i] = *(const float4*)(Qs + (ty + 16 * i) * SQ + (d4 << 2));
#pragma unroll
            for (int j = 0; j < 4; ++j)
                kv4[j] = *(const float4*)(Ks + (tx + 16 * j) * SKV + (d4 << 2));
#pragma unroll
            for (int i = 0; i < 4; ++i)
#pragma unroll
                for (int j = 0; j < 4; ++j)
                    s[i][j] += qv[i].x * kv4[j].x + qv[i].y * kv4[j].y
                             + qv[i].z * kv4[j].z + qv[i].w * kv4[j].w;
        }

        const bool diag = (kb == qb);

        // ---- masked online softmax (row stats replicated across the 16 tx lanes) ----
#pragma unroll
        for (int i = 0; i < 4; ++i) {
            const int r = ty + 16 * i;
            float mx = -1e30f;
#pragma unroll
            for (int j = 0; j < 4; ++j) {
                if (diag && (tx + 16 * j) > r) s[i][j] = -1e30f;
                mx = fmaxf(mx, s[i][j]);
            }
            mx = fmaxf(mx, __shfl_xor_sync(0xffffffffu, mx, 8));
            mx = fmaxf(mx, __shfl_xor_sync(0xffffffffu, mx, 4));
            mx = fmaxf(mx, __shfl_xor_sync(0xffffffffu, mx, 2));
            mx = fmaxf(mx, __shfl_xor_sync(0xffffffffu, mx, 1));

            const float mN   = fmaxf(m[i], mx);
            const float corr = __expf(m[i] - mN);
            m[i] = mN;

            float rs = 0.f;
#pragma unroll
            for (int j = 0; j < 4; ++j) {
                float p = __expf(s[i][j] - mN);
                Ps[r * SP + tx + 16 * j] = p;     // conflict-free: banks ty*16+tx
                rs += p;
            }
            rs += __shfl_xor_sync(0xffffffffu, rs, 8);
            rs += __shfl_xor_sync(0xffffffffu, rs, 4);
            rs += __shfl_xor_sync(0xffffffffu, rs, 2);
            rs += __shfl_xor_sync(0xffffffffu, rs, 1);

            l[i] = l[i] * corr + rs;
#pragma unroll
            for (int jj = 0; jj < 8; ++jj) o[i][jj] *= corr;
        }

        __syncthreads();       // P fully written before PV reads it

        // ---- PV: O[r][d] += P[r][kk] * V[kk][d]; d cols = {tx*4, 64+tx*4} ----
#pragma unroll 2
        for (int k4 = 0; k4 < 16; ++k4) {
            float4 pr[4];
#pragma unroll
            for (int i = 0; i < 4; ++i)
                pr[i] = *(const float4*)(Ps + (ty + 16 * i) * SP + (k4 << 2));
#pragma unroll
            for (int kk = 0; kk < 4; ++kk) {
                const float* vrow = Vs + (k4 * 4 + kk) * SKV + (tx << 2);
                float4 v0 = *(const float4*)(vrow);
                float4 v1 = *(const float4*)(vrow + 64);
#pragma unroll
                for (int i = 0; i < 4; ++i) {
                    float pw = (kk == 0) ? pr[i].x : (kk == 1) ? pr[i].y
                             : (kk == 2) ? pr[i].z : pr[i].w;
                    o[i][0] += pw * v0.x; o[i][1] += pw * v0.y;
                    o[i][2] += pw * v0.z; o[i][3] += pw * v0.w;
                    o[i][4] += pw * v1.x; o[i][5] += pw * v1.y;
                    o[i][6] += pw * v1.z; o[i][7] += pw * v1.w;
                }
            }
        }

        __syncthreads();       // everyone done reading V[buf] before we refill it

        if (it + 2 < nbt) {
            int kbn = (it + 2 < nvert) ? (kb0 + VSTRIDE * (it + 2))
                                       : (lstart + (it + 2) - nvert);
            load_kv_tile(sm, it & 1, kbn, k, v, hkv, tid);
        }
        cp_commit();           // exactly one group per iteration (may be empty)
    }

    // ---- epilogue: normalize and store ----
    float* og = out + (size_t)(qb * 64) * (NHEADS * HDIM) + h * HDIM;
#pragma unroll
    for (int i = 0; i < 4; ++i) {
        const float inv = 1.0f / l[i];
        const int r = ty + 16 * i;
        float4 a = make_float4(o[i][0] * inv, o[i][1] * inv, o[i][2] * inv, o[i][3] * inv);
        float4 b = make_float4(o[i][4] * inv, o[i][5] * inv, o[i][6] * inv, o[i][7] * inv);
        *(float4*)(og + r * (NHEADS * HDIM) + (tx << 2))      = a;
        *(float4*)(og + r * (NHEADS * HDIM) + 64 + (tx << 2)) = b;
    }
}

extern "C" void kernel_launch(void* const* d_in, const int* in_sizes, int n_in,
                              void* d_out, int out_size) {
    const float* q = (const float*)d_in[0];   // [2048, 4096] fp32
    const float* k = (const float*)d_in[1];   // [2048, 1024] fp32
    const float* v = (const float*)d_in[2];   // [2048, 1024] fp32
    float* out = (float*)d_out;               // [2048, 4096] fp32

    const int smem_bytes = SMEM_F * (int)sizeof(float);   // 189440 B
    cudaFuncSetAttribute(bsattn_fp32_kernel,
                         cudaFuncAttributeMaxDynamicSharedMemorySize, smem_bytes);

    dim3 grid(NHEADS * NBLK);   // 1024 CTAs: (head, q-block), big q-blocks first
    dim3 block(256);
    bsattn_fp32_kernel<<<grid, block, smem_bytes>>>(q, k, v, out);
}

// round 4
// speedup vs baseline: 1.1035x; 1.1035x over previous
#include <cuda_runtime.h>
#include <cstdint>

// Problem constants (Phi-3-small blocksparse prompt attention)
#define TOKENS   2048
#define NHEADS   32
#define NKV      8
#define HDIM     128
#define NBLK     32          // 2048 / 64
#define LOCALB   16
#define VSTRIDE  8
#define QKSCALE  0.08838834764831845f

// Shared memory strides (floats), chosen for conflict-free LDS.128 access
#define SQ  132              // Q row stride
#define SKV 132              // K/V row stride
#define SP  80               // P row stride

// Shared memory layout (float offsets)
#define OFF_Q   0
#define OFF_KV  (64 * SQ)                    // 8448
#define KVBUF   (2 * 64 * SKV)               // K tile + V tile per buffer = 16896
#define OFF_P   (OFF_KV + 2 * KVBUF)         // 42240
#define SMEM_F  (OFF_P + 64 * SP)            // 47360 floats = 189440 bytes

typedef unsigned long long u64;

// ---- packed fp32x2 math (Blackwell sm_103a; ptxas never emits these itself) ----
__device__ __forceinline__ u64 ffma2(u64 a, u64 b, u64 c) {
    u64 d;
    asm("fma.rn.f32x2 %0, %1, %2, %3;" : "=l"(d) : "l"(a), "l"(b), "l"(c));
    return d;
}
__device__ __forceinline__ u64 fmul2(u64 a, u64 b) {
    u64 d;
    asm("mul.rn.f32x2 %0, %1, %2;" : "=l"(d) : "l"(a), "l"(b));
    return d;
}
__device__ __forceinline__ u64 pack2(float lo, float hi) {
    u64 d; asm("mov.b64 %0, {%1, %2};" : "=l"(d) : "f"(lo), "f"(hi)); return d;
}
__device__ __forceinline__ float2 unpack2(u64 v) {
    float2 r; asm("mov.b64 {%0, %1}, %2;" : "=f"(r.x), "=f"(r.y) : "l"(v)); return r;
}

__device__ __forceinline__ void cpasync16(float* dst, const float* src) {
    unsigned s = (unsigned)__cvta_generic_to_shared(dst);
    asm volatile("cp.async.cg.shared.global [%0], [%1], 16;\n"
                 :: "r"(s), "l"(src) : "memory");
}
__device__ __forceinline__ void cp_commit() {
    asm volatile("cp.async.commit_group;\n" ::: "memory");
}
__device__ __forceinline__ void cp_wait1() {
    asm volatile("cp.async.wait_group 1;\n" ::: "memory");
}

// Stage one 64x128 K tile and one 64x128 V tile into smem buffer `buf`.
__device__ __forceinline__ void load_kv_tile(float* sm, int buf, int kb,
                                             const float* __restrict__ kg,
                                             const float* __restrict__ vg,
                                             int hkv, int tid) {
    float* Ks = sm + OFF_KV + buf * KVBUF;
    float* Vs = Ks + 64 * SKV;
    const float* kp = kg + (size_t)(kb * 64) * (NKV * HDIM) + hkv * HDIM;
    const float* vp = vg + (size_t)(kb * 64) * (NKV * HDIM) + hkv * HDIM;
#pragma unroll
    for (int u = 0; u < 8; ++u) {
        int t = tid + u * 256;
        int r = t >> 5;              // 64 rows, 32 chunks of 16B per row
        int c = (t & 31) << 2;       // float offset, 16B aligned
        cpasync16(Ks + r * SKV + c, kp + r * (NKV * HDIM) + c);
        cpasync16(Vs + r * SKV + c, vp + r * (NKV * HDIM) + c);
    }
}

__global__ void __launch_bounds__(256, 1)
bsattn_fp32x2_kernel(const float* __restrict__ q,
                     const float* __restrict__ k,
                     const float* __restrict__ v,
                     float* __restrict__ out) {
    extern __shared__ float sm[];
    const int tid = threadIdx.x;
    const int tx = tid & 15;          // 16 cols of thread grid
    const int ty = tid >> 4;          // 16 rows of thread grid
    const int bid = blockIdx.x;
    const int h  = bid & 31;
    const int qb = (NBLK - 1) - (bid >> 5);   // big q-blocks scheduled first
    const int hkv = h >> 2;                   // GQA: 4 query heads per kv head

    // ---- enumerate allowed key blocks: verticals (kb <= qb-16) then locals ----
    const int kb0 = (VSTRIDE - ((h + 1) & (VSTRIDE - 1))) & (VSTRIDE - 1);
    int nvert = 0;
    if (qb >= LOCALB && kb0 <= qb - LOCALB)
        nvert = (qb - LOCALB - kb0) / VSTRIDE + 1;
    int lstart = qb - (LOCALB - 1); if (lstart < 0) lstart = 0;
    const int nloc = qb - lstart + 1;
    const int nbt  = nvert + nloc;

    float* Qs = sm + OFF_Q;
    float* Ps = sm + OFF_P;

    // ---- prologue: prefetch first two K/V tiles (always commit 2 groups) ----
    {
        int kb_first = (0 < nvert) ? kb0 : lstart;
        load_kv_tile(sm, 0, kb_first, k, v, hkv, tid);
    }
    cp_commit();
    if (nbt > 1) {
        int kb_second = (1 < nvert) ? (kb0 + VSTRIDE) : (lstart + 1 - nvert);
        load_kv_tile(sm, 1, kb_second, k, v, hkv, tid);
    }
    cp_commit();

    // ---- load Q tile, pre-scaled by 1/sqrt(D) ----
    {
        const float* qg = q + (size_t)(qb * 64) * (NHEADS * HDIM) + h * HDIM;
#pragma unroll
        for (int u = 0; u < 8; ++u) {
            int t = tid + u * 256;
            int r = t >> 5;
            int c = (t & 31) << 2;
            float4 val = *(const float4*)(qg + r * (NHEADS * HDIM) + c);
            val.x *= QKSCALE; val.y *= QKSCALE; val.z *= QKSCALE; val.w *= QKSCALE;
            *(float4*)(Qs + r * SQ + c) = val;
        }
    }

    // ---- online-softmax state: thread owns rows {ty, ty+16, ty+32, ty+48} ----
    // O accumulators packed: o2[i][p] = fp32x2 pair of output dims
    //   p=0: {tx*4, tx*4+1}  p=1: {tx*4+2, tx*4+3}  p=2/3: same +64
    float m[4], l[4];
    u64 o2[4][4];
#pragma unroll
    for (int i = 0; i < 4; ++i) {
        m[i] = -1e30f; l[i] = 0.f;
#pragma unroll
        for (int jj = 0; jj < 4; ++jj) o2[i][jj] = 0ull;
    }

    for (int it = 0; it < nbt; ++it) {
        const int kb = (it < nvert) ? (kb0 + VSTRIDE * it) : (lstart + it - nvert);
        float* Ks = sm + OFF_KV + (it & 1) * KVBUF;
        float* Vs = Ks + 64 * SKV;

        cp_wait1();            // tile `it` landed (at most the it+1 load in flight)
        __syncthreads();       // visible to all threads; prev refill target safe

        // ---- QK: packed over d. acc2[i][j] holds (even-d partial, odd-d partial) ----
        u64 acc2[4][4];
#pragma unroll
        for (int i = 0; i < 4; ++i)
#pragma unroll
            for (int j = 0; j < 4; ++j) acc2[i][j] = 0ull;

#pragma unroll 4
        for (int d4 = 0; d4 < HDIM / 4; ++d4) {
            ulonglong2 qv[4], kv4[4];
#pragma unroll
            for (int i = 0; i < 4; ++i)
                qv[i] = *(const ulonglong2*)(Qs + (ty + 16 * i) * SQ + (d4 << 2));
#pragma unroll
            for (int j = 0; j < 4; ++j)
                kv4[j] = *(const ulonglong2*)(Ks + (tx + 16 * j) * SKV + (d4 << 2));
#pragma unroll
            for (int i = 0; i < 4; ++i)
#pragma unroll
                for (int j = 0; j < 4; ++j) {
                    acc2[i][j] = ffma2(qv[i].x, kv4[j].x, acc2[i][j]);
                    acc2[i][j] = ffma2(qv[i].y, kv4[j].y, acc2[i][j]);
                }
        }

        float s[4][4];
#pragma unroll
        for (int i = 0; i < 4; ++i)
#pragma unroll
            for (int j = 0; j < 4; ++j) {
                float2 t = unpack2(acc2[i][j]);
                s[i][j] = t.x + t.y;
            }

        const bool diag = (kb == qb);

        // ---- masked online softmax (row stats replicated across the 16 tx lanes) ----
#pragma unroll
        for (int i = 0; i < 4; ++i) {
            const int r = ty + 16 * i;
            float mx = -1e30f;
#pragma unroll
            for (int j = 0; j < 4; ++j) {
                if (diag && (tx + 16 * j) > r) s[i][j] = -1e30f;
                mx = fmaxf(mx, s[i][j]);
            }
            mx = fmaxf(mx, __shfl_xor_sync(0xffffffffu, mx, 8));
            mx = fmaxf(mx, __shfl_xor_sync(0xffffffffu, mx, 4));
            mx = fmaxf(mx, __shfl_xor_sync(0xffffffffu, mx, 2));
            mx = fmaxf(mx, __shfl_xor_sync(0xffffffffu, mx, 1));

            const float mN   = fmaxf(m[i], mx);
            const float corr = __expf(m[i] - mN);
            m[i] = mN;

            float rs = 0.f;
#pragma unroll
            for (int j = 0; j < 4; ++j) {
                float p = __expf(s[i][j] - mN);
                Ps[r * SP + tx + 16 * j] = p;     // conflict-free: banks ty*16+tx
                rs += p;
            }
            rs += __shfl_xor_sync(0xffffffffu, rs, 8);
            rs += __shfl_xor_sync(0xffffffffu, rs, 4);
            rs += __shfl_xor_sync(0xffffffffu, rs, 2);
            rs += __shfl_xor_sync(0xffffffffu, rs, 1);

            l[i] = l[i] * corr + rs;
            const u64 c2 = pack2(corr, corr);
#pragma unroll
            for (int jj = 0; jj < 4; ++jj) o2[i][jj] = fmul2(o2[i][jj], c2);
        }

        // P handoff is warp-local: row set {ty+16i} is written & read only by
        // the 16 threads sharing ty, all in this warp.
        __syncwarp();

        // ---- PV: packed over d. o2[i][p] += broadcast(p_row) * v2 ----
#pragma unroll 2
        for (int k4 = 0; k4 < 16; ++k4) {
            float4 pr[4];
#pragma unroll
            for (int i = 0; i < 4; ++i)
                pr[i] = *(const float4*)(Ps + (ty + 16 * i) * SP + (k4 << 2));
#pragma unroll
            for (int kk = 0; kk < 4; ++kk) {
                const float* vrow = Vs + (k4 * 4 + kk) * SKV + (tx << 2);
                ulonglong2 v0 = *(const ulonglong2*)(vrow);
                ulonglong2 v1 = *(const ulonglong2*)(vrow + 64);
#pragma unroll
                for (int i = 0; i < 4; ++i) {
                    float pw = (kk == 0) ? pr[i].x : (kk == 1) ? pr[i].y
                             : (kk == 2) ? pr[i].z : pr[i].w;
                    const u64 p2 = pack2(pw, pw);
                    o2[i][0] = ffma2(p2, v0.x, o2[i][0]);
                    o2[i][1] = ffma2(p2, v0.y, o2[i][1]);
                    o2[i][2] = ffma2(p2, v1.x, o2[i][2]);
                    o2[i][3] = ffma2(p2, v1.y, o2[i][3]);
                }
            }
        }

        __syncthreads();       // everyone done reading KV[buf] (and P) before reuse

        if (it + 2 < nbt) {
            int kbn = (it + 2 < nvert) ? (kb0 + VSTRIDE * (it + 2))
                                       : (lstart + (it + 2) - nvert);
            load_kv_tile(sm, it & 1, kbn, k, v, hkv, tid);
        }
        cp_commit();           // exactly one group per iteration (may be empty)
    }

    // ---- epilogue: normalize (packed) and store ----
    float* og = out + (size_t)(qb * 64) * (NHEADS * HDIM) + h * HDIM;
#pragma unroll
    for (int i = 0; i < 4; ++i) {
        const float inv = 1.0f / l[i];
        const u64 inv2 = pack2(inv, inv);
        const int r = ty + 16 * i;
        ulonglong2 a, b;
        a.x = fmul2(o2[i][0], inv2);
        a.y = fmul2(o2[i][1], inv2);
        b.x = fmul2(o2[i][2], inv2);
        b.y = fmul2(o2[i][3], inv2);
        *(ulonglong2*)(og + r * (NHEADS * HDIM) + (tx << 2))      = a;
        *(ulonglong2*)(og + r * (NHEADS * HDIM) + 64 + (tx << 2)) = b;
    }
}

extern "C" void kernel_launch(void* const* d_in, const int* in_sizes, int n_in,
                              void* d_out, int out_size) {
    const float* q = (const float*)d_in[0];   // [2048, 4096] fp32
    const float* k = (const float*)d_in[1];   // [2048, 1024] fp32
    const float* v = (const float*)d_in[2];   // [2048, 1024] fp32
    float* out = (float*)d_out;               // [2048, 4096] fp32

    const int smem_bytes = SMEM_F * (int)sizeof(float);   // 189440 B
    cudaFuncSetAttribute(bsattn_fp32x2_kernel,
                         cudaFuncAttributeMaxDynamicSharedMemorySize, smem_bytes);

    dim3 grid(NHEADS * NBLK);   // 1024 CTAs: (head, q-block), big q-blocks first
    dim3 block(256);
    bsattn_fp32x2_kernel<<<grid, block, smem_bytes>>>(q, k, v, out);
}

// round 5
// speedup vs baseline: 1.1063x; 1.0025x over previous
#include <cuda_runtime.h>
#include <cstdint>

// Problem constants (Phi-3-small blocksparse prompt attention)
#define TOKENS   2048
#define NHEADS   32
#define NKV      8
#define HDIM     128
#define NBLK     32          // 2048 / 64
#define LOCALB   16
#define VSTRIDE  8
#define QKSCALE  0.08838834764831845f

// Shared memory strides (floats), chosen for conflict-free LDS.128 access
#define SQ  132              // Q row stride
#define SKV 132              // K/V row stride
#define SP  80               // P row stride

// Shared memory layout (float offsets)
#define OFF_Q   0
#define OFF_KV  (64 * SQ)                    // 8448
#define KVBUF   (2 * 64 * SKV)               // K tile + V tile per buffer = 16896
#define OFF_P   (OFF_KV + 2 * KVBUF)         // 42240
#define SMEM_F  (OFF_P + 64 * SP)            // 47360 floats = 189440 bytes

typedef unsigned long long u64;

// ---- packed fp32x2 math (Blackwell sm_103a; ptxas never emits these itself) ----
__device__ __forceinline__ u64 ffma2(u64 a, u64 b, u64 c) {
    u64 d;
    asm("fma.rn.f32x2 %0, %1, %2, %3;" : "=l"(d) : "l"(a), "l"(b), "l"(c));
    return d;
}
__device__ __forceinline__ u64 fmul2(u64 a, u64 b) {
    u64 d;
    asm("mul.rn.f32x2 %0, %1, %2;" : "=l"(d) : "l"(a), "l"(b));
    return d;
}
__device__ __forceinline__ u64 pack2(float lo, float hi) {
    u64 d; asm("mov.b64 %0, {%1, %2};" : "=l"(d) : "f"(lo), "f"(hi)); return d;
}
__device__ __forceinline__ float2 unpack2(u64 v) {
    float2 r; asm("mov.b64 {%0, %1}, %2;" : "=f"(r.x), "=f"(r.y) : "l"(v)); return r;
}

__device__ __forceinline__ void cpasync16(float* dst, const float* src) {
    unsigned s = (unsigned)__cvta_generic_to_shared(dst);
    asm volatile("cp.async.cg.shared.global [%0], [%1], 16;\n"
                 :: "r"(s), "l"(src) : "memory");
}
__device__ __forceinline__ void cp_commit() {
    asm volatile("cp.async.commit_group;\n" ::: "memory");
}
__device__ __forceinline__ void cp_wait1() {
    asm volatile("cp.async.wait_group 1;\n" ::: "memory");
}

// Stage one 64x128 K tile and one 64x128 V tile into smem buffer `buf`.
__device__ __forceinline__ void load_kv_tile(float* sm, int buf, int kb,
                                             const float* __restrict__ kg,
                                             const float* __restrict__ vg,
                                             int hkv, int tid) {
    float* Ks = sm + OFF_KV + buf * KVBUF;
    float* Vs = Ks + 64 * SKV;
    const float* kp = kg + (size_t)(kb * 64) * (NKV * HDIM) + hkv * HDIM;
    const float* vp = vg + (size_t)(kb * 64) * (NKV * HDIM) + hkv * HDIM;
#pragma unroll
    for (int u = 0; u < 8; ++u) {
        int t = tid + u * 256;
        int r = t >> 5;              // 64 rows, 32 chunks of 16B per row
        int c = (t & 31) << 2;       // float offset, 16B aligned
        cpasync16(Ks + r * SKV + c, kp + r * (NKV * HDIM) + c);
        cpasync16(Vs + r * SKV + c, vp + r * (NKV * HDIM) + c);
    }
}

__global__ void __launch_bounds__(256, 1)
bsattn_fp32x2_kernel(const float* __restrict__ q,
                     const float* __restrict__ k,
                     const float* __restrict__ v,
                     float* __restrict__ out) {
    extern __shared__ float sm[];
    const int tid = threadIdx.x;
    const int tx = tid & 15;          // 16 cols of thread grid
    const int ty = tid >> 4;          // 16 rows of thread grid
    const int bid = blockIdx.x;
    const int h  = bid & 31;
    const int qb = (NBLK - 1) - (bid >> 5);   // big q-blocks scheduled first
    const int hkv = h >> 2;                   // GQA: 4 query heads per kv head

    // ---- enumerate allowed key blocks: verticals (kb <= qb-16) then locals ----
    const int kb0 = (VSTRIDE - ((h + 1) & (VSTRIDE - 1))) & (VSTRIDE - 1);
    int nvert = 0;
    if (qb >= LOCALB && kb0 <= qb - LOCALB)
        nvert = (qb - LOCALB - kb0) / VSTRIDE + 1;
    int lstart = qb - (LOCALB - 1); if (lstart < 0) lstart = 0;
    const int nloc = qb - lstart + 1;
    const int nbt  = nvert + nloc;

    float* Qs = sm + OFF_Q;
    float* Ps = sm + OFF_P;

    // ---- prologue: prefetch first two K/V tiles (always commit 2 groups) ----
    {
        int kb_first = (0 < nvert) ? kb0 : lstart;
        load_kv_tile(sm, 0, kb_first, k, v, hkv, tid);
    }
    cp_commit();
    if (nbt > 1) {
        int kb_second = (1 < nvert) ? (kb0 + VSTRIDE) : (lstart + 1 - nvert);
        load_kv_tile(sm, 1, kb_second, k, v, hkv, tid);
    }
    cp_commit();

    // ---- load Q tile, pre-scaled by 1/sqrt(D) ----
    {
        const float* qg = q + (size_t)(qb * 64) * (NHEADS * HDIM) + h * HDIM;
#pragma unroll
        for (int u = 0; u < 8; ++u) {
            int t = tid + u * 256;
            int r = t >> 5;
            int c = (t & 31) << 2;
            float4 val = *(const float4*)(qg + r * (NHEADS * HDIM) + c);
            val.x *= QKSCALE; val.y *= QKSCALE; val.z *= QKSCALE; val.w *= QKSCALE;
            *(float4*)(Qs + r * SQ + c) = val;
        }
    }

    // ---- online-softmax state: thread owns rows {ty, ty+16, ty+32, ty+48} ----
    // O accumulators packed: o2[i][p] = fp32x2 pair of output dims
    //   p=0: {tx*4, tx*4+1}  p=1: {tx*4+2, tx*4+3}  p=2/3: same +64
    float m[4], l[4];
    u64 o2[4][4];
#pragma unroll
    for (int i = 0; i < 4; ++i) {
        m[i] = -1e30f; l[i] = 0.f;
#pragma unroll
        for (int jj = 0; jj < 4; ++jj) o2[i][jj] = 0ull;
    }

    for (int it = 0; it < nbt; ++it) {
        const int kb = (it < nvert) ? (kb0 + VSTRIDE * it) : (lstart + it - nvert);
        float* Ks = sm + OFF_KV + (it & 1) * KVBUF;
        float* Vs = Ks + 64 * SKV;

        cp_wait1();            // tile `it` landed (at most the it+1 load in flight)
        __syncthreads();       // visible to all threads; prev refill target safe

        // ---- QK: packed over d. acc2[i][j] holds (even-d partial, odd-d partial) ----
        u64 acc2[4][4];
#pragma unroll
        for (int i = 0; i < 4; ++i)
#pragma unroll
            for (int j = 0; j < 4; ++j) acc2[i][j] = 0ull;

#pragma unroll 4
        for (int d4 = 0; d4 < HDIM / 4; ++d4) {
            ulonglong2 qv[4], kv4[4];
#pragma unroll
            for (int i = 0; i < 4; ++i)
                qv[i] = *(const ulonglong2*)(Qs + (ty + 16 * i) * SQ + (d4 << 2));
#pragma unroll
            for (int j = 0; j < 4; ++j)
                kv4[j] = *(const ulonglong2*)(Ks + (tx + 16 * j) * SKV + (d4 << 2));
#pragma unroll
            for (int i = 0; i < 4; ++i)
#pragma unroll
                for (int j = 0; j < 4; ++j) {
                    acc2[i][j] = ffma2(qv[i].x, kv4[j].x, acc2[i][j]);
                    acc2[i][j] = ffma2(qv[i].y, kv4[j].y, acc2[i][j]);
                }
        }

        float s[4][4];
#pragma unroll
        for (int i = 0; i < 4; ++i)
#pragma unroll
            for (int j = 0; j < 4; ++j) {
                float2 t = unpack2(acc2[i][j]);
                s[i][j] = t.x + t.y;
            }

        const bool diag = (kb == qb);

        // ---- masked online softmax (row stats replicated across the 16 tx lanes) ----
#pragma unroll
        for (int i = 0; i < 4; ++i) {
            const int r = ty + 16 * i;
            float mx = -1e30f;
#pragma unroll
            for (int j = 0; j < 4; ++j) {
                if (diag && (tx + 16 * j) > r) s[i][j] = -1e30f;
                mx = fmaxf(mx, s[i][j]);
            }
            mx = fmaxf(mx, __shfl_xor_sync(0xffffffffu, mx, 8));
            mx = fmaxf(mx, __shfl_xor_sync(0xffffffffu, mx, 4));
            mx = fmaxf(mx, __shfl_xor_sync(0xffffffffu, mx, 2));
            mx = fmaxf(mx, __shfl_xor_sync(0xffffffffu, mx, 1));

            const float mN   = fmaxf(m[i], mx);
            const float corr = __expf(m[i] - mN);
            m[i] = mN;

            float rs = 0.f;
#pragma unroll
            for (int j = 0; j < 4; ++j) {
                float p = __expf(s[i][j] - mN);
                Ps[r * SP + tx + 16 * j] = p;     // conflict-free: banks ty*16+tx
                rs += p;
            }
            rs += __shfl_xor_sync(0xffffffffu, rs, 8);
            rs += __shfl_xor_sync(0xffffffffu, rs, 4);
            rs += __shfl_xor_sync(0xffffffffu, rs, 2);
            rs += __shfl_xor_sync(0xffffffffu, rs, 1);

            l[i] = l[i] * corr + rs;
            const u64 c2 = pack2(corr, corr);
#pragma unroll
            for (int jj = 0; jj < 4; ++jj) o2[i][jj] = fmul2(o2[i][jj], c2);
        }

        // P handoff is warp-local: row set {ty+16i} is written & read only by
        // the 16 threads sharing ty, all in this warp.
        __syncwarp();

        // ---- PV: packed over d. o2[i][p] += broadcast(p_row) * v2 ----
#pragma unroll 2
        for (int k4 = 0; k4 < 16; ++k4) {
            float4 pr[4];
#pragma unroll
            for (int i = 0; i < 4; ++i)
                pr[i] = *(const float4*)(Ps + (ty + 16 * i) * SP + (k4 << 2));
#pragma unroll
            for (int kk = 0; kk < 4; ++kk) {
                const float* vrow = Vs + (k4 * 4 + kk) * SKV + (tx << 2);
                ulonglong2 v0 = *(const ulonglong2*)(vrow);
                ulonglong2 v1 = *(const ulonglong2*)(vrow + 64);
#pragma unroll
                for (int i = 0; i < 4; ++i) {
                    float pw = (kk == 0) ? pr[i].x : (kk == 1) ? pr[i].y
                             : (kk == 2) ? pr[i].z : pr[i].w;
                    const u64 p2 = pack2(pw, pw);
                    o2[i][0] = ffma2(p2, v0.x, o2[i][0]);
                    o2[i][1] = ffma2(p2, v0.y, o2[i][1]);
                    o2[i][2] = ffma2(p2, v1.x, o2[i][2]);
                    o2[i][3] = ffma2(p2, v1.y, o2[i][3]);
                }
            }
        }

        __syncthreads();       // everyone done reading KV[buf] (and P) before reuse

        if (it + 2 < nbt) {
            int kbn = (it + 2 < nvert) ? (kb0 + VSTRIDE * (it + 2))
                                       : (lstart + (it + 2) - nvert);
            load_kv_tile(sm, it & 1, kbn, k, v, hkv, tid);
        }
        cp_commit();           // exactly one group per iteration (may be empty)
    }

    // ---- epilogue: normalize (packed) and store ----
    float* og = out + (size_t)(qb * 64) * (NHEADS * HDIM) + h * HDIM;
#pragma unroll
    for (int i = 0; i < 4; ++i) {
        const float inv = 1.0f / l[i];
        const u64 inv2 = pack2(inv, inv);
        const int r = ty + 16 * i;
        ulonglong2 a, b;
        a.x = fmul2(o2[i][0], inv2);
        a.y = fmul2(o2[i][1], inv2);
        b.x = fmul2(o2[i][2], inv2);
        b.y = fmul2(o2[i][3], inv2);
        *(ulonglong2*)(og + r * (NHEADS * HDIM) + (tx << 2))      = a;
        *(ulonglong2*)(og + r * (NHEADS * HDIM) + 64 + (tx << 2)) = b;
    }
}

extern "C" void kernel_launch(void* const* d_in, const int* in_sizes, int n_in,
                              void* d_out, int out_size) {
    const float* q = (const float*)d_in[0];   // [2048, 4096] fp32
    const float* k = (const float*)d_in[1];   // [2048, 1024] fp32
    const float* v = (const float*)d_in[2];   // [2048, 1024] fp32
    float* out = (float*)d_out;               // [2048, 4096] fp32

    const int smem_bytes = SMEM_F * (int)sizeof(float);   // 189440 B
    cudaFuncSetAttribute(bsattn_fp32x2_kernel,
                         cudaFuncAttributeMaxDynamicSharedMemorySize, smem_bytes);

    dim3 grid(NHEADS * NBLK);   // 1024 CTAs: (head, q-block), big q-blocks first
    dim3 block(256);
    bsattn_fp32x2_kernel<<<grid, block, smem_bytes>>>(q, k, v, out);
}